// round 7
// baseline (speedup 1.0000x reference)
#include <cuda_runtime.h>
#include <cstdint>

#define F      1024
#define F4     256
#define DOMS   8
#define NBLK   296          // 2 CTAs/SM x 148 SMs (co-resident)
#define TPB    256
#define TILE   32           // rows per work ticket
#define EPSV   1e-5f

// ---------------- scratch (static device globals; no allocation) ----------------
__device__ unsigned g_count = 0, g_gen = 0;            // generation barrier
__device__ unsigned g_tickA = 0, g_tickC = 0;          // work tickets (self-resetting)
__device__ float    g_psum[(size_t)NBLK * DOMS * F];   // 9.7 MB
__device__ float    g_psq [(size_t)NBLK * DOMS * F];   // 9.7 MB
__device__ int      g_pcnt[NBLK * DOMS];
__device__ float    g_scale[DOMS * F];
__device__ float    g_bias [DOMS * F];

// generation barrier; master resets the ticket counter for the NEXT use
__device__ __forceinline__ void gsync(int resetA) {
    __syncthreads();
    if (threadIdx.x == 0) {
        unsigned my = *(volatile unsigned*)&g_gen;
        __threadfence();
        unsigned old = atomicAdd(&g_count, 1u);
        if (old == NBLK - 1u) {
            g_count = 0u;
            if (resetA) g_tickA = 0u; else g_tickC = 0u;
            __threadfence();
            atomicAdd(&g_gen, 1u);
        } else {
            while (*(volatile unsigned*)&g_gen == my) __nanosleep(32);
        }
        __threadfence();
    }
    __syncthreads();
}

#define ADD8(SA, QA) do { \
    SA.x += s.x; SA.y += s.y; SA.z += s.z; SA.w += s.w; \
    QA.x += q.x; QA.y += q.y; QA.z += q.z; QA.w += q.w; } while (0)

#define FLUSH_CUR() do { switch (cur) { \
    case 0: ADD8(sa0, qa0); break; case 1: ADD8(sa1, qa1); break; \
    case 2: ADD8(sa2, qa2); break; case 3: ADD8(sa3, qa3); break; \
    case 4: ADD8(sa4, qa4); break; case 5: ADD8(sa5, qa5); break; \
    case 6: ADD8(sa6, qa6); break; case 7: ADD8(sa7, qa7); break; \
    default: break; } } while (0)

__global__ void __launch_bounds__(TPB, 2) fused_k(
    const float4* __restrict__ x, const void* __restrict__ yv,
    const float* __restrict__ gamma, const float* __restrict__ beta,
    float4* __restrict__ out, int n)
{
    __shared__ int            ysm[TILE];
    __shared__ unsigned short perm[TILE];
    __shared__ unsigned char  dsort[TILE];
    __shared__ int            cnt[DOMS], off[DOMS], bcnt[DOMS], scnt[DOMS], cpart[64];
    __shared__ float          sred[9][28], qred[9][28];
    __shared__ unsigned       sh_t;

    const int tid = threadIdx.x;
    const int b   = blockIdx.x;
    const int NT  = (n + TILE - 1) / TILE;

    // ---- y dtype detection (int64 vs int32): int64 in [0,8) -> odd words zero ----
    int is64;
    {
        const unsigned* yw = (const unsigned*)yv;
        int lim = min(1024, (n - 1) / 2);
        int t = 0;
        for (int i = tid; i < lim; i += TPB)
            if (yw[2 * i + 1] != 0u) t = 1;
        is64 = __syncthreads_or(t) ? 0 : 1;
    }

    // ================= Phase A: dynamic tiles, per-domain register accumulators ====
    float4 sa0 = {0,0,0,0}, sa1 = {0,0,0,0}, sa2 = {0,0,0,0}, sa3 = {0,0,0,0};
    float4 sa4 = {0,0,0,0}, sa5 = {0,0,0,0}, sa6 = {0,0,0,0}, sa7 = {0,0,0,0};
    float4 qa0 = {0,0,0,0}, qa1 = {0,0,0,0}, qa2 = {0,0,0,0}, qa3 = {0,0,0,0};
    float4 qa4 = {0,0,0,0}, qa5 = {0,0,0,0}, qa6 = {0,0,0,0}, qa7 = {0,0,0,0};
    float4 s = {0,0,0,0}, q = {0,0,0,0};
    int cur = -1;

    if (tid < DOMS) bcnt[tid] = 0;

    for (;;) {
        __syncthreads();                            // smem reuse + bcnt init
        if (tid == 0) sh_t = atomicAdd(&g_tickA, 1u);
        if (tid < DOMS) cnt[tid] = 0;
        __syncthreads();
        unsigned t = sh_t;
        if (t >= (unsigned)NT) break;
        const int base = (int)t * TILE;
        const int nr   = min(TILE, n - base);

        if (tid < nr) {
            int d = is64 ? (int)((const long long*)yv)[base + tid]
                         : ((const int*)yv)[base + tid];
            ysm[tid] = d;
            atomicAdd(&cnt[d], 1);
        }
        __syncthreads();
        if (tid == 0) {
            int run = 0;
            #pragma unroll
            for (int d = 0; d < DOMS; d++) { off[d] = run; run += cnt[d]; }
        }
        if (tid < DOMS) bcnt[tid] += cnt[tid];
        __syncthreads();
        if (tid < nr) {
            int d = ysm[tid];
            int p = atomicAdd(&off[d], 1);
            perm[p]  = (unsigned short)tid;
            dsort[p] = (unsigned char)d;
        }
        __syncthreads();

        const float4* xb = x + (size_t)base * F4 + tid;
        int r = 0;
        for (; r + 4 <= nr; r += 4) {
            float4 v[4];
            #pragma unroll
            for (int i = 0; i < 4; i++)
                v[i] = xb[(size_t)perm[r + i] * F4];    // default: lives in L2 for phase C
            #pragma unroll
            for (int i = 0; i < 4; i++) {
                int d = dsort[r + i];
                if (d != cur) {                          // warp-uniform (sorted)
                    FLUSH_CUR();
                    s = make_float4(0.f, 0.f, 0.f, 0.f);
                    q = make_float4(0.f, 0.f, 0.f, 0.f);
                    cur = d;
                }
                s.x += v[i].x; s.y += v[i].y; s.z += v[i].z; s.w += v[i].w;
                q.x = fmaf(v[i].x, v[i].x, q.x);
                q.y = fmaf(v[i].y, v[i].y, q.y);
                q.z = fmaf(v[i].z, v[i].z, q.z);
                q.w = fmaf(v[i].w, v[i].w, q.w);
            }
        }
        for (; r < nr; r++) {
            int d = dsort[r];
            float4 v = xb[(size_t)perm[r] * F4];
            if (d != cur) {
                FLUSH_CUR();
                s = make_float4(0.f, 0.f, 0.f, 0.f);
                q = make_float4(0.f, 0.f, 0.f, 0.f);
                cur = d;
            }
            s.x += v.x; s.y += v.y; s.z += v.z; s.w += v.w;
            q.x = fmaf(v.x, v.x, q.x); q.y = fmaf(v.y, v.y, q.y);
            q.z = fmaf(v.z, v.z, q.z); q.w = fmaf(v.w, v.w, q.w);
        }
    }
    FLUSH_CUR();

    {   // write per-block partials (evict-first: dead after phase B)
        float4* psum = (float4*)(g_psum + (size_t)b * DOMS * F);
        float4* psq  = (float4*)(g_psq  + (size_t)b * DOMS * F);
        __stcs(&psum[0 * F4 + tid], sa0); __stcs(&psq[0 * F4 + tid], qa0);
        __stcs(&psum[1 * F4 + tid], sa1); __stcs(&psq[1 * F4 + tid], qa1);
        __stcs(&psum[2 * F4 + tid], sa2); __stcs(&psq[2 * F4 + tid], qa2);
        __stcs(&psum[3 * F4 + tid], sa3); __stcs(&psq[3 * F4 + tid], qa3);
        __stcs(&psum[4 * F4 + tid], sa4); __stcs(&psq[4 * F4 + tid], qa4);
        __stcs(&psum[5 * F4 + tid], sa5); __stcs(&psq[5 * F4 + tid], qa5);
        __stcs(&psum[6 * F4 + tid], sa6); __stcs(&psq[6 * F4 + tid], qa6);
        __stcs(&psum[7 * F4 + tid], sa7); __stcs(&psq[7 * F4 + tid], qa7);
        if (tid < DOMS) g_pcnt[b * DOMS + tid] = bcnt[tid];
    }

    gsync(1);   // master resets ticket A for next launch

    // ================= Phase B: distributed reduce -> (scale, bias) table =================
    {
        if (tid < 64) {
            int d = tid & 7, g = tid >> 3;
            int s0 = g * 37, s1 = min(NBLK, s0 + 37);
            int c = 0;
            for (int sl = s0; sl < s1; sl++) c += g_pcnt[sl * DOMS + d];
            cpart[tid] = c;
        }
        __syncthreads();
        if (tid < DOMS) {
            int c = 0;
            #pragma unroll
            for (int g = 0; g < 8; g++) c += cpart[g * 8 + tid];
            scnt[tid] = c;
        }

        const int start = b * 28;                   // 296*28 >= 8192
        const int p = tid % 28, c = tid / 28;       // c in 0..9 (c==9 idle)
        if (c < 9 && start + p < DOMS * F) {
            int j  = start + p;
            int s0 = c * 33, s1 = min(NBLK, s0 + 33);
            float ss = 0.f, qq = 0.f;
            for (int sl = s0; sl < s1; sl++) {
                ss += __ldcs(&g_psum[(size_t)sl * (DOMS * F) + j]);
                qq += __ldcs(&g_psq [(size_t)sl * (DOMS * F) + j]);
            }
            sred[c][p] = ss; qred[c][p] = qq;
        }
        __syncthreads();
        if (tid < 28 && start + tid < DOMS * F) {
            int jj = start + tid;
            float ss = 0.f, qq = 0.f;
            #pragma unroll
            for (int cc = 0; cc < 9; cc++) { ss += sred[cc][tid]; qq += qred[cc][tid]; }
            int d = jj >> 10, f = jj & (F - 1);
            float cf = (float)scnt[d];
            float sc, bi;
            if (cf > 1.f) {
                float inv  = 1.f / cf;
                float mean = ss * inv;
                float var  = fmaxf(qq * inv - mean * mean, 0.f);
                sc = gamma[f] * rsqrtf(var + EPSV);
                bi = fmaf(-mean, sc, beta[f]);
            } else if (cf == 1.f) { sc = 1.f; bi = 0.f; }   // count==1 -> raw x
            else                  { sc = 0.f; bi = 0.f; }   // count==0 -> 0
            g_scale[jj] = sc;
            g_bias [jj] = bi;
        }
    }

    gsync(0);   // master resets ticket C for next launch

    // ================= Phase C: dynamic descending tiles (global LIFO L2 replay) ====
    {
        const float4* sc4 = (const float4*)g_scale;
        const float4* bi4 = (const float4*)g_bias;

        for (;;) {
            __syncthreads();                        // protect ysm reuse
            if (tid == 0) sh_t = atomicAdd(&g_tickC, 1u);
            __syncthreads();
            unsigned u = sh_t;
            if (u >= (unsigned)NT) break;
            const int t    = NT - 1 - (int)u;
            const int base = t * TILE;
            const int nr   = min(TILE, n - base);

            if (tid < nr)
                ysm[tid] = is64 ? (int)((const long long*)yv)[base + tid]
                                : ((const int*)yv)[base + tid];
            __syncthreads();

            const float4* xc = x   + (size_t)base * F4 + tid;
            float4*       oc = out + (size_t)base * F4 + tid;

            int r = nr - 1;
            for (; r - 7 >= 0; r -= 8) {
                float4 v[8];
                #pragma unroll
                for (int i = 0; i < 8; i++)
                    v[i] = __ldcs(xc + (size_t)(r - i) * F4);
                #pragma unroll
                for (int i = 0; i < 8; i++) {
                    int row = r - i;
                    int d   = ysm[row];
                    float4 sc = sc4[d * F4 + tid];  // 64 KB table: L1/L2-resident
                    float4 bi = bi4[d * F4 + tid];
                    float4 o;
                    o.x = fmaf(v[i].x, sc.x, bi.x);
                    o.y = fmaf(v[i].y, sc.y, bi.y);
                    o.z = fmaf(v[i].z, sc.z, bi.z);
                    o.w = fmaf(v[i].w, sc.w, bi.w);
                    __stcs(oc + (size_t)row * F4, o);
                }
            }
            for (; r >= 0; r--) {
                int d = ysm[r];
                float4 v  = __ldcs(xc + (size_t)r * F4);
                float4 sc = sc4[d * F4 + tid];
                float4 bi = bi4[d * F4 + tid];
                float4 o;
                o.x = fmaf(v.x, sc.x, bi.x);
                o.y = fmaf(v.y, sc.y, bi.y);
                o.z = fmaf(v.z, sc.z, bi.z);
                o.w = fmaf(v.w, sc.w, bi.w);
                __stcs(oc + (size_t)r * F4, o);
            }
        }
    }
}

// ---------------- launch ----------------
extern "C" void kernel_launch(void* const* d_in, const int* in_sizes, int n_in,
                              void* d_out, int out_size) {
    const float4* x     = (const float4*)d_in[0];
    const void*   y     = d_in[1];
    const float*  gamma = (const float*)d_in[2];
    const float*  beta  = (const float*)d_in[3];
    float4*       out   = (float4*)d_out;

    int n = in_sizes[1];   // batch (y element count)

    fused_k<<<NBLK, TPB>>>(x, y, gamma, beta, out, n);
}

// round 8
// speedup vs baseline: 1.0860x; 1.0860x over previous
#include <cuda_runtime.h>
#include <cstdint>

#define F      1024
#define F4     256
#define DOMS   8
#define NBLK   296          // 2 CTAs/SM x 148 SMs (co-resident)
#define TPB    256
#define RMAX   256          // rows per block: ceil(65536/296)=222
#define EPSV   1e-5f

// ---------------- scratch (static device globals; no allocation) ----------------
__device__ unsigned g_count = 0, g_gen = 0;            // generation barrier
__device__ float    g_psum[(size_t)NBLK * DOMS * F];   // 9.7 MB
__device__ float    g_psq [(size_t)NBLK * DOMS * F];   // 9.7 MB
__device__ int      g_pcnt[NBLK * DOMS];
__device__ float    g_scale[DOMS * F];
__device__ float    g_bias [DOMS * F];

// generation-based grid barrier (self-resetting; graph-replay safe)
__device__ __forceinline__ void gsync() {
    __syncthreads();
    if (threadIdx.x == 0) {
        unsigned my = *(volatile unsigned*)&g_gen;
        __threadfence();
        unsigned old = atomicAdd(&g_count, 1u);
        if (old == NBLK - 1u) {
            g_count = 0u;
            __threadfence();
            atomicAdd(&g_gen, 1u);
        } else {
            while (*(volatile unsigned*)&g_gen == my) __nanosleep(32);
        }
        __threadfence();
    }
    __syncthreads();
}

// accumulate float4 vv into (SA,QA)
#define ACC(SA, QA) do { \
    SA.x += vv.x; SA.y += vv.y; SA.z += vv.z; SA.w += vv.w; \
    QA.x = fmaf(vv.x, vv.x, QA.x); QA.y = fmaf(vv.y, vv.y, QA.y); \
    QA.z = fmaf(vv.z, vv.z, QA.z); QA.w = fmaf(vv.w, vv.w, QA.w); } while (0)

#define ACC_SWITCH(D) do { switch (D) { \
    case 0: ACC(sa0, qa0); break; case 1: ACC(sa1, qa1); break; \
    case 2: ACC(sa2, qa2); break; case 3: ACC(sa3, qa3); break; \
    case 4: ACC(sa4, qa4); break; case 5: ACC(sa5, qa5); break; \
    case 6: ACC(sa6, qa6); break; default: ACC(sa7, qa7); break; } } while (0)

__global__ void __launch_bounds__(TPB, 2) fused_k(
    const float4* __restrict__ x, const void* __restrict__ yv,
    const float* __restrict__ gamma, const float* __restrict__ beta,
    float4* __restrict__ out, int n)
{
    __shared__ int   ysm[RMAX];
    __shared__ int   cnt[DOMS], scnt[DOMS], cpart[64];
    __shared__ float sred[9][28], qred[9][28];

    const int tid   = threadIdx.x;
    const int b     = blockIdx.x;
    const int rpb   = (n + NBLK - 1) / NBLK;        // 222 for n=65536
    const int base  = b * rpb;
    const int nrows = min(rpb, n - base);

    // ---- y dtype detection (int64 vs int32): int64 in [0,8) -> odd words zero ----
    int is64;
    {
        const unsigned* yw = (const unsigned*)yv;
        int lim = min(1024, (n - 1) / 2);
        int t = 0;
        for (int i = tid; i < lim; i += TPB)
            if (yw[2 * i + 1] != 0u) t = 1;
        is64 = __syncthreads_or(t) ? 0 : 1;
    }

    // ---- load this block's y values + per-domain counts (no sort) ----
    if (tid < DOMS) cnt[tid] = 0;
    __syncthreads();
    if (tid < nrows) {
        int d = is64 ? (int)((const long long*)yv)[base + tid]
                     : ((const int*)yv)[base + tid];
        ysm[tid] = d;
        atomicAdd(&cnt[d], 1);
    }
    __syncthreads();

    // ================= Phase A: LINEAR ascending stream, switch-accumulate ========
    float4 sa0 = {0,0,0,0}, sa1 = {0,0,0,0}, sa2 = {0,0,0,0}, sa3 = {0,0,0,0};
    float4 sa4 = {0,0,0,0}, sa5 = {0,0,0,0}, sa6 = {0,0,0,0}, sa7 = {0,0,0,0};
    float4 qa0 = {0,0,0,0}, qa1 = {0,0,0,0}, qa2 = {0,0,0,0}, qa3 = {0,0,0,0};
    float4 qa4 = {0,0,0,0}, qa5 = {0,0,0,0}, qa6 = {0,0,0,0}, qa7 = {0,0,0,0};

    {
        const float4* xb = x + (size_t)base * F4 + tid;
        int r = 0;
        for (; r + 8 <= nrows; r += 8) {
            float4 v[8]; int dd[8];
            #pragma unroll
            for (int i = 0; i < 8; i++) {
                v[i]  = xb[(size_t)(r + i) * F4];   // sequential: stays in L2 for phase C
                dd[i] = ysm[r + i];
            }
            #pragma unroll
            for (int i = 0; i < 8; i++) {
                float4 vv = v[i];
                ACC_SWITCH(dd[i]);                  // warp-uniform (d constant per row)
            }
        }
        for (; r < nrows; r++) {
            float4 vv = xb[(size_t)r * F4];
            int d = ysm[r];
            ACC_SWITCH(d);
        }
    }

    {   // write per-block partials (evict-first: dead after phase B)
        float4* psum = (float4*)(g_psum + (size_t)b * DOMS * F);
        float4* psq  = (float4*)(g_psq  + (size_t)b * DOMS * F);
        __stcs(&psum[0 * F4 + tid], sa0); __stcs(&psq[0 * F4 + tid], qa0);
        __stcs(&psum[1 * F4 + tid], sa1); __stcs(&psq[1 * F4 + tid], qa1);
        __stcs(&psum[2 * F4 + tid], sa2); __stcs(&psq[2 * F4 + tid], qa2);
        __stcs(&psum[3 * F4 + tid], sa3); __stcs(&psq[3 * F4 + tid], qa3);
        __stcs(&psum[4 * F4 + tid], sa4); __stcs(&psq[4 * F4 + tid], qa4);
        __stcs(&psum[5 * F4 + tid], sa5); __stcs(&psq[5 * F4 + tid], qa5);
        __stcs(&psum[6 * F4 + tid], sa6); __stcs(&psq[6 * F4 + tid], qa6);
        __stcs(&psum[7 * F4 + tid], sa7); __stcs(&psq[7 * F4 + tid], qa7);
        if (tid < DOMS) g_pcnt[b * DOMS + tid] = (nrows > 0) ? cnt[tid] : 0;
    }

    gsync();

    // ================= Phase B: distributed reduce -> (scale, bias) table =========
    {
        if (tid < 64) {
            int d = tid & 7, g = tid >> 3;
            int s0 = g * 37, s1 = min(NBLK, s0 + 37);
            int c = 0;
            for (int sl = s0; sl < s1; sl++) c += g_pcnt[sl * DOMS + d];
            cpart[tid] = c;
        }
        __syncthreads();
        if (tid < DOMS) {
            int c = 0;
            #pragma unroll
            for (int g = 0; g < 8; g++) c += cpart[g * 8 + tid];
            scnt[tid] = c;
        }

        const int start = b * 28;                   // 296*28 >= 8192
        const int p = tid % 28, c = tid / 28;       // c in 0..9 (c==9 idle)
        if (c < 9 && start + p < DOMS * F) {
            int j  = start + p;
            int s0 = c * 33, s1 = min(NBLK, s0 + 33);
            float ss = 0.f, qq = 0.f;
            for (int sl = s0; sl < s1; sl++) {
                ss += __ldcs(&g_psum[(size_t)sl * (DOMS * F) + j]);
                qq += __ldcs(&g_psq [(size_t)sl * (DOMS * F) + j]);
            }
            sred[c][p] = ss; qred[c][p] = qq;
        }
        __syncthreads();
        if (tid < 28 && start + tid < DOMS * F) {
            int jj = start + tid;
            float ss = 0.f, qq = 0.f;
            #pragma unroll
            for (int cc = 0; cc < 9; cc++) { ss += sred[cc][tid]; qq += qred[cc][tid]; }
            int d = jj >> 10, f = jj & (F - 1);
            float cf = (float)scnt[d];
            float sc, bi;
            if (cf > 1.f) {
                float inv  = 1.f / cf;
                float mean = ss * inv;
                float var  = fmaxf(qq * inv - mean * mean, 0.f);
                sc = gamma[f] * rsqrtf(var + EPSV);
                bi = fmaf(-mean, sc, beta[f]);
            } else if (cf == 1.f) { sc = 1.f; bi = 0.f; }   // count==1 -> raw x
            else                  { sc = 0.f; bi = 0.f; }   // count==0 -> 0
            g_scale[jj] = sc;
            g_bias [jj] = bi;
        }
    }

    gsync();

    // ================= Phase C: LINEAR descending stream (LRU inverse of A) =======
    {
        const float4* sc4 = (const float4*)g_scale;
        const float4* bi4 = (const float4*)g_bias;
        const float4* xc  = x   + (size_t)base * F4 + tid;
        float4*       oc  = out + (size_t)base * F4 + tid;

        int r = nrows - 1;
        for (; r - 7 >= 0; r -= 8) {
            float4 v[8]; int dd[8];
            #pragma unroll
            for (int i = 0; i < 8; i++) {
                v[i]  = __ldcs(xc + (size_t)(r - i) * F4);
                dd[i] = ysm[r - i];
            }
            #pragma unroll
            for (int i = 0; i < 8; i++) {
                float4 sc = sc4[dd[i] * F4 + tid];  // 64 KB table: L1-resident
                float4 bi = bi4[dd[i] * F4 + tid];
                float4 o;
                o.x = fmaf(v[i].x, sc.x, bi.x);
                o.y = fmaf(v[i].y, sc.y, bi.y);
                o.z = fmaf(v[i].z, sc.z, bi.z);
                o.w = fmaf(v[i].w, sc.w, bi.w);
                __stcs(oc + (size_t)(r - i) * F4, o);
            }
        }
        for (; r >= 0; r--) {
            int d = ysm[r];
            float4 v  = __ldcs(xc + (size_t)r * F4);
            float4 sc = sc4[d * F4 + tid];
            float4 bi = bi4[d * F4 + tid];
            float4 o;
            o.x = fmaf(v.x, sc.x, bi.x);
            o.y = fmaf(v.y, sc.y, bi.y);
            o.z = fmaf(v.z, sc.z, bi.z);
            o.w = fmaf(v.w, sc.w, bi.w);
            __stcs(oc + (size_t)r * F4, o);
        }
    }
}

// ---------------- launch ----------------
extern "C" void kernel_launch(void* const* d_in, const int* in_sizes, int n_in,
                              void* d_out, int out_size) {
    const float4* x     = (const float4*)d_in[0];
    const void*   y     = d_in[1];
    const float*  gamma = (const float*)d_in[2];
    const float*  beta  = (const float*)d_in[3];
    float4*       out   = (float4*)d_out;

    int n = in_sizes[1];   // batch (y element count)

    fused_k<<<NBLK, TPB>>>(x, y, gamma, beta, out, n);
}

// round 9
// speedup vs baseline: 1.0895x; 1.0033x over previous
#include <cuda_runtime.h>
#include <cstdint>

#define F      1024
#define F4     256
#define DOMS   8
#define NBLK   296          // 2 CTAs/SM x 148 SMs
#define TPB    256
#define RMAX   256          // rows per block: ceil(65536/296)=222
#define EPSV   1e-5f

// ---------------- scratch (static device globals; no allocation) ----------------
__device__ float g_psum[(size_t)NBLK * DOMS * F];   // 9.7 MB
__device__ float g_psq [(size_t)NBLK * DOMS * F];   // 9.7 MB
__device__ int   g_pcnt[NBLK * DOMS];
__device__ float g_scale[DOMS * F];
__device__ float g_bias [DOMS * F];

// accumulate float4 vv into (SA,QA)
#define ACC(SA, QA) do { \
    SA.x += vv.x; SA.y += vv.y; SA.z += vv.z; SA.w += vv.w; \
    QA.x = fmaf(vv.x, vv.x, QA.x); QA.y = fmaf(vv.y, vv.y, QA.y); \
    QA.z = fmaf(vv.z, vv.z, QA.z); QA.w = fmaf(vv.w, vv.w, QA.w); } while (0)

#define ACC_SWITCH(D) do { switch (D) { \
    case 0: ACC(sa0, qa0); break; case 1: ACC(sa1, qa1); break; \
    case 2: ACC(sa2, qa2); break; case 3: ACC(sa3, qa3); break; \
    case 4: ACC(sa4, qa4); break; case 5: ACC(sa5, qa5); break; \
    case 6: ACC(sa6, qa6); break; default: ACC(sa7, qa7); break; } } while (0)

// ---- y dtype detection (int64 vs int32): int64 in [0,8) -> odd words zero ----
__device__ __forceinline__ int detect_is64(const void* yv, int n, int tid) {
    const unsigned* yw = (const unsigned*)yv;
    int lim = min(1024, (n - 1) / 2);
    int t = 0;
    for (int i = tid; i < lim; i += TPB)
        if (yw[2 * i + 1] != 0u) t = 1;
    return __syncthreads_or(t) ? 0 : 1;
}

// ================= K1: per-block stats, linear ascending stream =================
__global__ void __launch_bounds__(TPB, 2) stats_k(
    const float4* __restrict__ x, const void* __restrict__ yv, int n)
{
    __shared__ int ysm[RMAX];
    __shared__ int cnt[DOMS];

    const int tid   = threadIdx.x;
    const int b     = blockIdx.x;
    const int rpb   = (n + NBLK - 1) / NBLK;
    const int base  = b * rpb;
    const int nrows = min(rpb, n - base);

    int is64 = detect_is64(yv, n, tid);

    if (tid < DOMS) cnt[tid] = 0;
    __syncthreads();
    if (tid < nrows) {
        int d = is64 ? (int)((const long long*)yv)[base + tid]
                     : ((const int*)yv)[base + tid];
        ysm[tid] = d;
        atomicAdd(&cnt[d], 1);
    }
    __syncthreads();

    float4 sa0 = {0,0,0,0}, sa1 = {0,0,0,0}, sa2 = {0,0,0,0}, sa3 = {0,0,0,0};
    float4 sa4 = {0,0,0,0}, sa5 = {0,0,0,0}, sa6 = {0,0,0,0}, sa7 = {0,0,0,0};
    float4 qa0 = {0,0,0,0}, qa1 = {0,0,0,0}, qa2 = {0,0,0,0}, qa3 = {0,0,0,0};
    float4 qa4 = {0,0,0,0}, qa5 = {0,0,0,0}, qa6 = {0,0,0,0}, qa7 = {0,0,0,0};

    {
        const float4* xb = x + (size_t)base * F4 + tid;
        int r = 0;
        for (; r + 8 <= nrows; r += 8) {
            float4 v[8]; int dd[8];
            #pragma unroll
            for (int i = 0; i < 8; i++) {
                v[i]  = xb[(size_t)(r + i) * F4];   // default policy: stays in L2 for K3
                dd[i] = ysm[r + i];
            }
            #pragma unroll
            for (int i = 0; i < 8; i++) {
                float4 vv = v[i];
                ACC_SWITCH(dd[i]);                  // warp-uniform
            }
        }
        for (; r < nrows; r++) {
            float4 vv = xb[(size_t)r * F4];
            int d = ysm[r];
            ACC_SWITCH(d);
        }
    }

    float4* psum = (float4*)(g_psum + (size_t)b * DOMS * F);
    float4* psq  = (float4*)(g_psq  + (size_t)b * DOMS * F);
    __stcs(&psum[0 * F4 + tid], sa0); __stcs(&psq[0 * F4 + tid], qa0);
    __stcs(&psum[1 * F4 + tid], sa1); __stcs(&psq[1 * F4 + tid], qa1);
    __stcs(&psum[2 * F4 + tid], sa2); __stcs(&psq[2 * F4 + tid], qa2);
    __stcs(&psum[3 * F4 + tid], sa3); __stcs(&psq[3 * F4 + tid], qa3);
    __stcs(&psum[4 * F4 + tid], sa4); __stcs(&psq[4 * F4 + tid], qa4);
    __stcs(&psum[5 * F4 + tid], sa5); __stcs(&psq[5 * F4 + tid], qa5);
    __stcs(&psum[6 * F4 + tid], sa6); __stcs(&psq[6 * F4 + tid], qa6);
    __stcs(&psum[7 * F4 + tid], sa7); __stcs(&psq[7 * F4 + tid], qa7);
    if (tid < DOMS) g_pcnt[b * DOMS + tid] = (nrows > 0) ? cnt[tid] : 0;
}

// ================= K2: distributed partial reduce -> (scale, bias) table =========
__global__ void __launch_bounds__(TPB, 2) table_k(
    const float* __restrict__ gamma, const float* __restrict__ beta)
{
    __shared__ int   scnt[DOMS], cpart[64];
    __shared__ float sred[9][28], qred[9][28];

    const int tid = threadIdx.x;
    const int b   = blockIdx.x;

    if (tid < 64) {
        int d = tid & 7, g = tid >> 3;
        int s0 = g * 37, s1 = min(NBLK, s0 + 37);
        int c = 0;
        for (int sl = s0; sl < s1; sl++) c += g_pcnt[sl * DOMS + d];
        cpart[tid] = c;
    }
    __syncthreads();
    if (tid < DOMS) {
        int c = 0;
        #pragma unroll
        for (int g = 0; g < 8; g++) c += cpart[g * 8 + tid];
        scnt[tid] = c;
    }

    const int start = b * 28;                   // 296*28 >= 8192
    const int p = tid % 28, c = tid / 28;       // c in 0..9 (c==9 idle)
    if (c < 9 && start + p < DOMS * F) {
        int j  = start + p;
        int s0 = c * 33, s1 = min(NBLK, s0 + 33);
        float ss = 0.f, qq = 0.f;
        for (int sl = s0; sl < s1; sl++) {
            ss += __ldcs(&g_psum[(size_t)sl * (DOMS * F) + j]);   // dead after this
            qq += __ldcs(&g_psq [(size_t)sl * (DOMS * F) + j]);
        }
        sred[c][p] = ss; qred[c][p] = qq;
    }
    __syncthreads();
    if (tid < 28 && start + tid < DOMS * F) {
        int jj = start + tid;
        float ss = 0.f, qq = 0.f;
        #pragma unroll
        for (int cc = 0; cc < 9; cc++) { ss += sred[cc][tid]; qq += qred[cc][tid]; }
        int d = jj >> 10, f = jj & (F - 1);
        float cf = (float)scnt[d];
        float sc, bi;
        if (cf > 1.f) {
            float inv  = 1.f / cf;
            float mean = ss * inv;
            float var  = fmaxf(qq * inv - mean * mean, 0.f);
            sc = gamma[f] * rsqrtf(var + EPSV);
            bi = fmaf(-mean, sc, beta[f]);
        } else if (cf == 1.f) { sc = 1.f; bi = 0.f; }   // count==1 -> raw x
        else                  { sc = 0.f; bi = 0.f; }   // count==0 -> 0
        g_scale[jj] = sc;
        g_bias [jj] = bi;
    }
}

// ================= K3: normalize, linear descending stream (LRU inverse of K1) ====
__global__ void __launch_bounds__(TPB, 2) norm_k(
    const float4* __restrict__ x, const void* __restrict__ yv,
    float4* __restrict__ out, int n)
{
    __shared__ int ysm[RMAX];

    const int tid   = threadIdx.x;
    const int b     = blockIdx.x;
    const int rpb   = (n + NBLK - 1) / NBLK;
    const int base  = b * rpb;
    const int nrows = min(rpb, n - base);

    int is64 = detect_is64(yv, n, tid);

    if (tid < nrows)
        ysm[tid] = is64 ? (int)((const long long*)yv)[base + tid]
                        : ((const int*)yv)[base + tid];
    __syncthreads();

    const float4* sc4 = (const float4*)g_scale;
    const float4* bi4 = (const float4*)g_bias;
    const float4* xc  = x   + (size_t)base * F4 + tid;
    float4*       oc  = out + (size_t)base * F4 + tid;

    int r = nrows - 1;
    for (; r - 7 >= 0; r -= 8) {
        float4 v[8]; int dd[8];
        #pragma unroll
        for (int i = 0; i < 8; i++) {
            v[i]  = __ldcs(xc + (size_t)(r - i) * F4);
            dd[i] = ysm[r - i];
        }
        #pragma unroll
        for (int i = 0; i < 8; i++) {
            float4 sc = sc4[dd[i] * F4 + tid];  // 64 KB table: L1-resident
            float4 bi = bi4[dd[i] * F4 + tid];
            float4 o;
            o.x = fmaf(v[i].x, sc.x, bi.x);
            o.y = fmaf(v[i].y, sc.y, bi.y);
            o.z = fmaf(v[i].z, sc.z, bi.z);
            o.w = fmaf(v[i].w, sc.w, bi.w);
            __stcs(oc + (size_t)(r - i) * F4, o);
        }
    }
    for (; r >= 0; r--) {
        int d = ysm[r];
        float4 v  = __ldcs(xc + (size_t)r * F4);
        float4 sc = sc4[d * F4 + tid];
        float4 bi = bi4[d * F4 + tid];
        float4 o;
        o.x = fmaf(v.x, sc.x, bi.x);
        o.y = fmaf(v.y, sc.y, bi.y);
        o.z = fmaf(v.z, sc.z, bi.z);
        o.w = fmaf(v.w, sc.w, bi.w);
        __stcs(oc + (size_t)r * F4, o);
    }
}

// ---------------- launch ----------------
extern "C" void kernel_launch(void* const* d_in, const int* in_sizes, int n_in,
                              void* d_out, int out_size) {
    const float4* x     = (const float4*)d_in[0];
    const void*   y     = d_in[1];
    const float*  gamma = (const float*)d_in[2];
    const float*  beta  = (const float*)d_in[3];
    float4*       out   = (float4*)d_out;

    int n = in_sizes[1];   // batch (y element count)

    stats_k<<<NBLK, TPB>>>(x, y, n);
    table_k<<<NBLK, TPB>>>(gamma, beta);
    norm_k <<<NBLK, TPB>>>(x, y, out, n);
}

// round 10
// speedup vs baseline: 1.1209x; 1.0287x over previous
#include <cuda_runtime.h>
#include <cstdint>

#define F      1024
#define F4     256
#define DOMS   8
#define NBLK   296          // 2 CTAs/SM x 148 SMs
#define TPB    256
#define RMAX   256          // rows per block: ceil(65536/296)=222
#define EPSV   1e-5f

// ---------------- scratch (static device globals; no allocation) ----------------
__device__ float g_psum[(size_t)NBLK * DOMS * F];   // 9.7 MB
__device__ float g_psq [(size_t)NBLK * DOMS * F];   // 9.7 MB
__device__ int   g_pcnt[NBLK * DOMS];
__device__ float g_scale[DOMS * F];
__device__ float g_bias [DOMS * F];

// accumulate float4 vv into (SA,QA)
#define ACC(SA, QA) do { \
    SA.x += vv.x; SA.y += vv.y; SA.z += vv.z; SA.w += vv.w; \
    QA.x = fmaf(vv.x, vv.x, QA.x); QA.y = fmaf(vv.y, vv.y, QA.y); \
    QA.z = fmaf(vv.z, vv.z, QA.z); QA.w = fmaf(vv.w, vv.w, QA.w); } while (0)

#define ACC_SWITCH(D) do { switch (D) { \
    case 0: ACC(sa0, qa0); break; case 1: ACC(sa1, qa1); break; \
    case 2: ACC(sa2, qa2); break; case 3: ACC(sa3, qa3); break; \
    case 4: ACC(sa4, qa4); break; case 5: ACC(sa5, qa5); break; \
    case 6: ACC(sa6, qa6); break; default: ACC(sa7, qa7); break; } } while (0)

// load 4-row group G into (VB, DB); consume accumulates a group
#define LOADG(VB, DB, G) do { int _rr = (G) * 4; \
    _Pragma("unroll") for (int _i = 0; _i < 4; _i++) { \
        VB[_i] = xb[(size_t)(_rr + _i) * F4]; DB[_i] = ysm[_rr + _i]; } } while (0)

#define CONSUME(VB, DB) do { \
    _Pragma("unroll") for (int _i = 0; _i < 4; _i++) { \
        float4 vv = VB[_i]; ACC_SWITCH(DB[_i]); } } while (0)

// ---- y dtype detection (int64 vs int32): int64 in [0,8) -> odd words zero ----
__device__ __forceinline__ int detect_is64(const void* yv, int n, int tid) {
    const unsigned* yw = (const unsigned*)yv;
    int lim = min(1024, (n - 1) / 2);
    int t = 0;
    for (int i = tid; i < lim; i += TPB)
        if (yw[2 * i + 1] != 0u) t = 1;
    return __syncthreads_or(t) ? 0 : 1;
}

// ================= K1: per-block stats, software-pipelined linear stream =========
__global__ void __launch_bounds__(TPB, 2) stats_k(
    const float4* __restrict__ x, const void* __restrict__ yv, int n)
{
    __shared__ int ysm[RMAX];
    __shared__ int cnt[DOMS];

    const int tid   = threadIdx.x;
    const int b     = blockIdx.x;
    const int rpb   = (n + NBLK - 1) / NBLK;
    const int base  = b * rpb;
    const int nrows = min(rpb, n - base);

    int is64 = detect_is64(yv, n, tid);

    if (tid < DOMS) cnt[tid] = 0;
    __syncthreads();
    if (tid < nrows) {
        int d = is64 ? (int)((const long long*)yv)[base + tid]
                     : ((const int*)yv)[base + tid];
        ysm[tid] = d;
        atomicAdd(&cnt[d], 1);
    }
    __syncthreads();

    float4 sa0 = {0,0,0,0}, sa1 = {0,0,0,0}, sa2 = {0,0,0,0}, sa3 = {0,0,0,0};
    float4 sa4 = {0,0,0,0}, sa5 = {0,0,0,0}, sa6 = {0,0,0,0}, sa7 = {0,0,0,0};
    float4 qa0 = {0,0,0,0}, qa1 = {0,0,0,0}, qa2 = {0,0,0,0}, qa3 = {0,0,0,0};
    float4 qa4 = {0,0,0,0}, qa5 = {0,0,0,0}, qa6 = {0,0,0,0}, qa7 = {0,0,0,0};

    {
        const float4* xb = x + (size_t)base * F4 + tid;
        const int k = nrows >> 2;                   // full 4-row groups
        float4 vA[4], vB[4]; int dA[4], dB[4];

        if (k > 0) {
            LOADG(vA, dA, 0);                       // prologue
            int g = 1;
            for (; g + 1 < k; g += 2) {             // steady state: load-ahead
                LOADG(vB, dB, g);
                CONSUME(vA, dA);
                LOADG(vA, dA, g + 1);
                CONSUME(vB, dB);
            }
            if (g < k) {
                LOADG(vB, dB, g);
                CONSUME(vA, dA);
                CONSUME(vB, dB);
            } else {
                CONSUME(vA, dA);
            }
        }
        for (int r = k * 4; r < nrows; r++) {       // tail rows
            float4 vv = xb[(size_t)r * F4];
            int d = ysm[r];
            ACC_SWITCH(d);
        }
    }

    float4* psum = (float4*)(g_psum + (size_t)b * DOMS * F);
    float4* psq  = (float4*)(g_psq  + (size_t)b * DOMS * F);
    __stcs(&psum[0 * F4 + tid], sa0); __stcs(&psq[0 * F4 + tid], qa0);
    __stcs(&psum[1 * F4 + tid], sa1); __stcs(&psq[1 * F4 + tid], qa1);
    __stcs(&psum[2 * F4 + tid], sa2); __stcs(&psq[2 * F4 + tid], qa2);
    __stcs(&psum[3 * F4 + tid], sa3); __stcs(&psq[3 * F4 + tid], qa3);
    __stcs(&psum[4 * F4 + tid], sa4); __stcs(&psq[4 * F4 + tid], qa4);
    __stcs(&psum[5 * F4 + tid], sa5); __stcs(&psq[5 * F4 + tid], qa5);
    __stcs(&psum[6 * F4 + tid], sa6); __stcs(&psq[6 * F4 + tid], qa6);
    __stcs(&psum[7 * F4 + tid], sa7); __stcs(&psq[7 * F4 + tid], qa7);
    if (tid < DOMS) g_pcnt[b * DOMS + tid] = (nrows > 0) ? cnt[tid] : 0;
}

// ================= K2: distributed partial reduce -> (scale, bias) table =========
__global__ void __launch_bounds__(TPB, 2) table_k(
    const float* __restrict__ gamma, const float* __restrict__ beta)
{
    __shared__ int   scnt[DOMS], cpart[64];
    __shared__ float sred[9][28], qred[9][28];

    const int tid = threadIdx.x;
    const int b   = blockIdx.x;

    if (tid < 64) {
        int d = tid & 7, g = tid >> 3;
        int s0 = g * 37, s1 = min(NBLK, s0 + 37);
        int c = 0;
        for (int sl = s0; sl < s1; sl++) c += g_pcnt[sl * DOMS + d];
        cpart[tid] = c;
    }
    __syncthreads();
    if (tid < DOMS) {
        int c = 0;
        #pragma unroll
        for (int g = 0; g < 8; g++) c += cpart[g * 8 + tid];
        scnt[tid] = c;
    }

    const int start = b * 28;                   // 296*28 >= 8192
    const int p = tid % 28, c = tid / 28;       // c in 0..9 (c==9 idle)
    if (c < 9 && start + p < DOMS * F) {
        int j  = start + p;
        int s0 = c * 33, s1 = min(NBLK, s0 + 33);
        float ss = 0.f, qq = 0.f;
        for (int sl = s0; sl < s1; sl++) {
            ss += __ldcs(&g_psum[(size_t)sl * (DOMS * F) + j]);   // dead after this
            qq += __ldcs(&g_psq [(size_t)sl * (DOMS * F) + j]);
        }
        sred[c][p] = ss; qred[c][p] = qq;
    }
    __syncthreads();
    if (tid < 28 && start + tid < DOMS * F) {
        int jj = start + tid;
        float ss = 0.f, qq = 0.f;
        #pragma unroll
        for (int cc = 0; cc < 9; cc++) { ss += sred[cc][tid]; qq += qred[cc][tid]; }
        int d = jj >> 10, f = jj & (F - 1);
        float cf = (float)scnt[d];
        float sc, bi;
        if (cf > 1.f) {
            float inv  = 1.f / cf;
            float mean = ss * inv;
            float var  = fmaxf(qq * inv - mean * mean, 0.f);
            sc = gamma[f] * rsqrtf(var + EPSV);
            bi = fmaf(-mean, sc, beta[f]);
        } else if (cf == 1.f) { sc = 1.f; bi = 0.f; }   // count==1 -> raw x
        else                  { sc = 0.f; bi = 0.f; }   // count==0 -> 0
        g_scale[jj] = sc;
        g_bias [jj] = bi;
    }
}

// ================= K3: normalize, software-pipelined descending stream ===========
__global__ void __launch_bounds__(TPB, 2) norm_k(
    const float4* __restrict__ x, const void* __restrict__ yv,
    float4* __restrict__ out, int n)
{
    __shared__ int ysm[RMAX];

    const int tid   = threadIdx.x;
    const int b     = blockIdx.x;
    const int rpb   = (n + NBLK - 1) / NBLK;
    const int base  = b * rpb;
    const int nrows = min(rpb, n - base);

    int is64 = detect_is64(yv, n, tid);

    if (tid < nrows)
        ysm[tid] = is64 ? (int)((const long long*)yv)[base + tid]
                        : ((const int*)yv)[base + tid];
    __syncthreads();

    const float4* sc4 = (const float4*)g_scale;
    const float4* bi4 = (const float4*)g_bias;
    const float4* xc  = x   + (size_t)base * F4 + tid;
    float4*       oc  = out + (size_t)base * F4 + tid;

    const int k = nrows >> 2;                       // full 4-row groups

    // tail rows first (descending), so overall order is strictly descending
    for (int r = nrows - 1; r >= k * 4; r--) {
        int d = ysm[r];
        float4 v  = __ldcs(xc + (size_t)r * F4);
        float4 sc = sc4[d * F4 + tid];
        float4 bi = bi4[d * F4 + tid];
        float4 o;
        o.x = fmaf(v.x, sc.x, bi.x);
        o.y = fmaf(v.y, sc.y, bi.y);
        o.z = fmaf(v.z, sc.z, bi.z);
        o.w = fmaf(v.w, sc.w, bi.w);
        __stcs(oc + (size_t)r * F4, o);
    }

#define NLOAD(VB, DB, G) do { int _rr = (G) * 4; \
    _Pragma("unroll") for (int _i = 0; _i < 4; _i++) { \
        VB[_i] = __ldcs(xc + (size_t)(_rr + _i) * F4); DB[_i] = ysm[_rr + _i]; } } while (0)

#define NSTORE(VB, DB, G) do { int _rr = (G) * 4; \
    _Pragma("unroll") for (int _i = 0; _i < 4; _i++) { \
        float4 sc = sc4[DB[_i] * F4 + tid]; \
        float4 bi = bi4[DB[_i] * F4 + tid]; \
        float4 o; \
        o.x = fmaf(VB[_i].x, sc.x, bi.x); \
        o.y = fmaf(VB[_i].y, sc.y, bi.y); \
        o.z = fmaf(VB[_i].z, sc.z, bi.z); \
        o.w = fmaf(VB[_i].w, sc.w, bi.w); \
        __stcs(oc + (size_t)(_rr + _i) * F4, o); } } while (0)

    if (k > 0) {
        float4 vA[4], vB[4]; int dA[4], dB[4];
        NLOAD(vA, dA, k - 1);                       // prologue (highest group)
        int g = k - 2;
        for (; g - 0 >= 1; g -= 2) {                // steady state: load-ahead
            NLOAD(vB, dB, g);
            NSTORE(vA, dA, g + 1);
            NLOAD(vA, dA, g - 1);
            NSTORE(vB, dB, g);
        }
        if (g == 0) {
            NLOAD(vB, dB, 0);
            NSTORE(vA, dA, 1);
            NSTORE(vB, dB, 0);
        } else {
            NSTORE(vA, dA, 0);
        }
    }
}

// ---------------- launch ----------------
extern "C" void kernel_launch(void* const* d_in, const int* in_sizes, int n_in,
                              void* d_out, int out_size) {
    const float4* x     = (const float4*)d_in[0];
    const void*   y     = d_in[1];
    const float*  gamma = (const float*)d_in[2];
    const float*  beta  = (const float*)d_in[3];
    float4*       out   = (float4*)d_out;

    int n = in_sizes[1];   // batch (y element count)

    stats_k<<<NBLK, TPB>>>(x, y, n);
    table_k<<<NBLK, TPB>>>(gamma, beta);
    norm_k <<<NBLK, TPB>>>(x, y, out, n);
}

// round 11
// speedup vs baseline: 1.1540x; 1.0296x over previous
#include <cuda_runtime.h>
#include <cstdint>

#define F      1024
#define F4     256
#define DOMS   8
#define NBLK   296          // 2 CTAs/SM x 148 SMs
#define TPB    256
#define RMAX   256          // rows per block: ceil(65536/296)=222
#define KEEP   76           // rows/block kept L2-resident for norm_k (92 MB total)
#define EPSV   1e-5f

// ---------------- scratch (static device globals; no allocation) ----------------
__device__ float g_psum[(size_t)NBLK * DOMS * F];   // 9.7 MB (L2-resident by budget)
__device__ float g_psq [(size_t)NBLK * DOMS * F];   // 9.7 MB
__device__ int   g_pcnt[NBLK * DOMS];
__device__ float g_scale[DOMS * F];
__device__ float g_bias [DOMS * F];

// accumulate float4 vv into (SA,QA)
#define ACC(SA, QA) do { \
    SA.x += vv.x; SA.y += vv.y; SA.z += vv.z; SA.w += vv.w; \
    QA.x = fmaf(vv.x, vv.x, QA.x); QA.y = fmaf(vv.y, vv.y, QA.y); \
    QA.z = fmaf(vv.z, vv.z, QA.z); QA.w = fmaf(vv.w, vv.w, QA.w); } while (0)

#define ACC_SWITCH(D) do { switch (D) { \
    case 0: ACC(sa0, qa0); break; case 1: ACC(sa1, qa1); break; \
    case 2: ACC(sa2, qa2); break; case 3: ACC(sa3, qa3); break; \
    case 4: ACC(sa4, qa4); break; case 5: ACC(sa5, qa5); break; \
    case 6: ACC(sa6, qa6); break; default: ACC(sa7, qa7); break; } } while (0)

// group loaders: evict-first (streamed) vs default (L2-kept)
#define LOADG_CS(VB, DB, G) do { int _rr = (G) * 4; \
    _Pragma("unroll") for (int _i = 0; _i < 4; _i++) { \
        VB[_i] = __ldcs(xb + (size_t)(_rr + _i) * F4); DB[_i] = ysm[_rr + _i]; } } while (0)

#define LOADG_DF(VB, DB, G) do { int _rr = (G) * 4; \
    _Pragma("unroll") for (int _i = 0; _i < 4; _i++) { \
        VB[_i] = xb[(size_t)(_rr + _i) * F4]; DB[_i] = ysm[_rr + _i]; } } while (0)

#define CONSUME(VB, DB) do { \
    _Pragma("unroll") for (int _i = 0; _i < 4; _i++) { \
        float4 vv = VB[_i]; ACC_SWITCH(DB[_i]); } } while (0)

// double-buffered pipelined accumulate over group range [GBEG, GEND)
#define PIPE(GBEG, GEND, LOADM) do { \
    if ((GEND) > (GBEG)) { \
        LOADM(vA, dA, (GBEG)); \
        int g = (GBEG) + 1; \
        for (; g + 1 < (GEND); g += 2) { \
            LOADM(vB, dB, g);     CONSUME(vA, dA); \
            LOADM(vA, dA, g + 1); CONSUME(vB, dB); \
        } \
        if (g < (GEND)) { LOADM(vB, dB, g); CONSUME(vA, dA); CONSUME(vB, dB); } \
        else            { CONSUME(vA, dA); } \
    } } while (0)

// ---- y dtype detection (int64 vs int32): int64 in [0,8) -> odd words zero ----
__device__ __forceinline__ int detect_is64(const void* yv, int n, int tid) {
    const unsigned* yw = (const unsigned*)yv;
    int lim = min(1024, (n - 1) / 2);
    int t = 0;
    for (int i = tid; i < lim; i += TPB)
        if (yw[2 * i + 1] != 0u) t = 1;
    return __syncthreads_or(t) ? 0 : 1;
}

// ================= K1: stats; early rows streamed, last KEEP rows L2-kept ========
__global__ void __launch_bounds__(TPB, 2) stats_k(
    const float4* __restrict__ x, const void* __restrict__ yv, int n)
{
    __shared__ int ysm[RMAX];
    __shared__ int cnt[DOMS];

    const int tid   = threadIdx.x;
    const int b     = blockIdx.x;
    const int rpb   = (n + NBLK - 1) / NBLK;
    const int base  = b * rpb;
    const int nrows = min(rpb, n - base);

    int is64 = detect_is64(yv, n, tid);

    if (tid < DOMS) cnt[tid] = 0;
    __syncthreads();
    if (tid < nrows) {
        int d = is64 ? (int)((const long long*)yv)[base + tid]
                     : ((const int*)yv)[base + tid];
        ysm[tid] = d;
        atomicAdd(&cnt[d], 1);
    }
    __syncthreads();

    float4 sa0 = {0,0,0,0}, sa1 = {0,0,0,0}, sa2 = {0,0,0,0}, sa3 = {0,0,0,0};
    float4 sa4 = {0,0,0,0}, sa5 = {0,0,0,0}, sa6 = {0,0,0,0}, sa7 = {0,0,0,0};
    float4 qa0 = {0,0,0,0}, qa1 = {0,0,0,0}, qa2 = {0,0,0,0}, qa3 = {0,0,0,0};
    float4 qa4 = {0,0,0,0}, qa5 = {0,0,0,0}, qa6 = {0,0,0,0}, qa7 = {0,0,0,0};

    {
        const float4* xb = x + (size_t)base * F4 + tid;
        const int k    = nrows >> 2;                     // total full 4-row groups
        const int cut4 = max(0, nrows - KEEP) >> 2;      // groups streamed (evict-first)
        float4 vA[4], vB[4]; int dA[4], dB[4];

        PIPE(0, cut4, LOADG_CS);                         // rows that can't survive in L2
        PIPE(cut4, k, LOADG_DF);                         // keep-set: resident for norm_k
        for (int r = k * 4; r < nrows; r++) {            // tail rows (default: kept)
            float4 vv = xb[(size_t)r * F4];
            int d = ysm[r];
            ACC_SWITCH(d);
        }
    }

    // partials: DEFAULT policy -> stay L2-resident for table_k (19.4 MB budget)
    float4* psum = (float4*)(g_psum + (size_t)b * DOMS * F);
    float4* psq  = (float4*)(g_psq  + (size_t)b * DOMS * F);
    psum[0 * F4 + tid] = sa0; psq[0 * F4 + tid] = qa0;
    psum[1 * F4 + tid] = sa1; psq[1 * F4 + tid] = qa1;
    psum[2 * F4 + tid] = sa2; psq[2 * F4 + tid] = qa2;
    psum[3 * F4 + tid] = sa3; psq[3 * F4 + tid] = qa3;
    psum[4 * F4 + tid] = sa4; psq[4 * F4 + tid] = qa4;
    psum[5 * F4 + tid] = sa5; psq[5 * F4 + tid] = qa5;
    psum[6 * F4 + tid] = sa6; psq[6 * F4 + tid] = qa6;
    psum[7 * F4 + tid] = sa7; psq[7 * F4 + tid] = qa7;
    if (tid < DOMS) g_pcnt[b * DOMS + tid] = (nrows > 0) ? cnt[tid] : 0;
}

// ================= K2: distributed partial reduce -> (scale, bias) table =========
__global__ void __launch_bounds__(TPB, 2) table_k(
    const float* __restrict__ gamma, const float* __restrict__ beta)
{
    __shared__ int   scnt[DOMS], cpart[64];
    __shared__ float sred[9][28], qred[9][28];

    const int tid = threadIdx.x;
    const int b   = blockIdx.x;

    if (tid < 64) {
        int d = tid & 7, g = tid >> 3;
        int s0 = g * 37, s1 = min(NBLK, s0 + 37);
        int c = 0;
        for (int sl = s0; sl < s1; sl++) c += g_pcnt[sl * DOMS + d];
        cpart[tid] = c;
    }
    __syncthreads();
    if (tid < DOMS) {
        int c = 0;
        #pragma unroll
        for (int g = 0; g < 8; g++) c += cpart[g * 8 + tid];
        scnt[tid] = c;
    }

    const int start = b * 28;                   // 296*28 >= 8192
    const int p = tid % 28, c = tid / 28;       // c in 0..9 (c==9 idle)
    if (c < 9 && start + p < DOMS * F) {
        int j  = start + p;
        int s0 = c * 33, s1 = min(NBLK, s0 + 33);
        float ss = 0.f, qq = 0.f;
        for (int sl = s0; sl < s1; sl++) {
            ss += g_psum[(size_t)sl * (DOMS * F) + j];   // expect L2 hits
            qq += g_psq [(size_t)sl * (DOMS * F) + j];
        }
        sred[c][p] = ss; qred[c][p] = qq;
    }
    __syncthreads();
    if (tid < 28 && start + tid < DOMS * F) {
        int jj = start + tid;
        float ss = 0.f, qq = 0.f;
        #pragma unroll
        for (int cc = 0; cc < 9; cc++) { ss += sred[cc][tid]; qq += qred[cc][tid]; }
        int d = jj >> 10, f = jj & (F - 1);
        float cf = (float)scnt[d];
        float sc, bi;
        if (cf > 1.f) {
            float inv  = 1.f / cf;
            float mean = ss * inv;
            float var  = fmaxf(qq * inv - mean * mean, 0.f);
            sc = gamma[f] * rsqrtf(var + EPSV);
            bi = fmaf(-mean, sc, beta[f]);
        } else if (cf == 1.f) { sc = 1.f; bi = 0.f; }   // count==1 -> raw x
        else                  { sc = 0.f; bi = 0.f; }   // count==0 -> 0
        g_scale[jj] = sc;
        g_bias [jj] = bi;
    }
}

// ================= K3: normalize, pipelined descending stream (hits keep-set) ====
__global__ void __launch_bounds__(TPB, 2) norm_k(
    const float4* __restrict__ x, const void* __restrict__ yv,
    float4* __restrict__ out, int n)
{
    __shared__ int ysm[RMAX];

    const int tid   = threadIdx.x;
    const int b     = blockIdx.x;
    const int rpb   = (n + NBLK - 1) / NBLK;
    const int base  = b * rpb;
    const int nrows = min(rpb, n - base);

    int is64 = detect_is64(yv, n, tid);

    if (tid < nrows)
        ysm[tid] = is64 ? (int)((const long long*)yv)[base + tid]
                        : ((const int*)yv)[base + tid];
    __syncthreads();

    const float4* sc4 = (const float4*)g_scale;
    const float4* bi4 = (const float4*)g_bias;
    const float4* xc  = x   + (size_t)base * F4 + tid;
    float4*       oc  = out + (size_t)base * F4 + tid;

    const int k = nrows >> 2;                       // full 4-row groups

    // tail rows first (descending), so overall order is strictly descending
    for (int r = nrows - 1; r >= k * 4; r--) {
        int d = ysm[r];
        float4 v  = __ldcs(xc + (size_t)r * F4);
        float4 sc = sc4[d * F4 + tid];
        float4 bi = bi4[d * F4 + tid];
        float4 o;
        o.x = fmaf(v.x, sc.x, bi.x);
        o.y = fmaf(v.y, sc.y, bi.y);
        o.z = fmaf(v.z, sc.z, bi.z);
        o.w = fmaf(v.w, sc.w, bi.w);
        __stcs(oc + (size_t)r * F4, o);
    }

#define NLOAD(VB, DB, G) do { int _rr = (G) * 4; \
    _Pragma("unroll") for (int _i = 0; _i < 4; _i++) { \
        VB[_i] = __ldcs(xc + (size_t)(_rr + _i) * F4); DB[_i] = ysm[_rr + _i]; } } while (0)

#define NSTORE(VB, DB, G) do { int _rr = (G) * 4; \
    _Pragma("unroll") for (int _i = 0; _i < 4; _i++) { \
        float4 sc = sc4[DB[_i] * F4 + tid]; \
        float4 bi = bi4[DB[_i] * F4 + tid]; \
        float4 o; \
        o.x = fmaf(VB[_i].x, sc.x, bi.x); \
        o.y = fmaf(VB[_i].y, sc.y, bi.y); \
        o.z = fmaf(VB[_i].z, sc.z, bi.z); \
        o.w = fmaf(VB[_i].w, sc.w, bi.w); \
        __stcs(oc + (size_t)(_rr + _i) * F4, o); } } while (0)

    if (k > 0) {
        float4 vA[4], vB[4]; int dA[4], dB[4];
        NLOAD(vA, dA, k - 1);                       // prologue (highest group)
        int g = k - 2;
        for (; g >= 1; g -= 2) {                    // steady state: load-ahead
            NLOAD(vB, dB, g);
            NSTORE(vA, dA, g + 1);
            NLOAD(vA, dA, g - 1);
            NSTORE(vB, dB, g);
        }
        if (g == 0) {
            NLOAD(vB, dB, 0);
            NSTORE(vA, dA, 1);
            NSTORE(vB, dB, 0);
        } else {
            NSTORE(vA, dA, 0);
        }
    }
}

// ---------------- launch ----------------
extern "C" void kernel_launch(void* const* d_in, const int* in_sizes, int n_in,
                              void* d_out, int out_size) {
    const float4* x     = (const float4*)d_in[0];
    const void*   y     = d_in[1];
    const float*  gamma = (const float*)d_in[2];
    const float*  beta  = (const float*)d_in[3];
    float4*       out   = (float4*)d_out;

    int n = in_sizes[1];   // batch (y element count)

    stats_k<<<NBLK, TPB>>>(x, y, n);
    table_k<<<NBLK, TPB>>>(gamma, beta);
    norm_k <<<NBLK, TPB>>>(x, y, out, n);
}